// round 14
// baseline (speedup 1.0000x reference)
#include <cuda_runtime.h>
#include <cuda_fp16.h>
#include <math.h>
#include <stdint.h>

#define T_TOK 8192
#define DIM   1024
#define HID   2048
#define NE    8
#define TEMPR 5.0f
#define EPSG  1e-9f

#define BM 96
#define BN 128
#define BK 64
#define NTHR 192
#define NSTAGE 3
// stage layout (128B rows): A = 96x128B; B = 128x128B
#define OFF_A  0
#define OFF_B  (BM*128)                 // 12288
#define STAGE  (BM*128 + BN*128)        // 28672
#define SMEM_DYN (NSTAGE*STAGE)         // 86016  (x2 CTAs/SM = 172032)

// ---------------- scratch ----------------
__device__ int   g_cnt[NE];
__device__ int   g_base[NE];
__device__ int   g_bucket[NE][T_TOK];
__device__ float g_gate[2 * T_TOK];
__device__ __half g_x16[(size_t)T_TOK * DIM];
__device__ __half g_w1[(size_t)NE * DIM * HID];    // transposed [e][h][d], fp16
__device__ __half g_w2[(size_t)NE * HID * DIM];    // transposed [e][d][h], fp16
__device__ __half g_h16[(size_t)2 * T_TOK * HID];  // contiguous per expert
__device__ float g_y[(size_t)2 * T_TOK * DIM];

// ---------------- helpers ----------------
__device__ __forceinline__ uint32_t smem_u32(const void* p) {
    uint32_t r;
    asm("{ .reg .u64 t; cvta.to.shared.u64 t, %1; cvt.u32.u64 %0, t; }" : "=r"(r) : "l"(p));
    return r;
}
__device__ __forceinline__ void cp16(uint32_t dst, const void* src) {
    asm volatile("cp.async.cg.shared.global [%0], [%1], 16;" :: "r"(dst), "l"(src));
}
__device__ __forceinline__ void cp_commit() {
    asm volatile("cp.async.commit_group;" ::: "memory");
}
__device__ __forceinline__ void cp_wait1() {
    asm volatile("cp.async.wait_group 1;" ::: "memory");
}
__device__ __forceinline__ void cp_wait0() {
    asm volatile("cp.async.wait_group 0;" ::: "memory");
}
__device__ __forceinline__ void ldm_x4(uint32_t* r, uint32_t addr) {
    asm volatile("ldmatrix.sync.aligned.m8n8.x4.shared.b16 {%0,%1,%2,%3}, [%4];"
                 : "=r"(r[0]), "=r"(r[1]), "=r"(r[2]), "=r"(r[3]) : "r"(addr));
}
__device__ __forceinline__ void mma_fp16(float* d, const uint32_t* a, const uint32_t* b) {
    asm volatile(
        "mma.sync.aligned.m16n8k16.row.col.f32.f16.f16.f32 "
        "{%0,%1,%2,%3}, {%4,%5,%6,%7}, {%8,%9}, {%0,%1,%2,%3};"
        : "+f"(d[0]), "+f"(d[1]), "+f"(d[2]), "+f"(d[3])
        : "r"(a[0]), "r"(a[1]), "r"(a[2]), "r"(a[3]), "r"(b[0]), "r"(b[1]));
}
__device__ __forceinline__ float gelu_exact(float v) {
    return 0.5f * v * (1.0f + erff(v * 0.70710678118654752f));
}
__device__ __forceinline__ uint32_t pack_h16(__half a, __half b) {
    return ((uint32_t)__half_as_ushort(b) << 16) | (uint32_t)__half_as_ushort(a);
}

// ---------------- kernel 1: convert x to fp16 (also zeroes g_cnt) ----------------
__global__ void k_split_x(const float* __restrict__ x) {
    if (blockIdx.x == 0 && threadIdx.x < NE) g_cnt[threadIdx.x] = 0;
    size_t i = ((size_t)blockIdx.x * blockDim.x + threadIdx.x) * 4;
    if (i >= (size_t)T_TOK * DIM) return;
    float4 v = *reinterpret_cast<const float4*>(x + i);
    uint2 p;
    p.x = pack_h16(__float2half_rn(v.x), __float2half_rn(v.y));
    p.y = pack_h16(__float2half_rn(v.z), __float2half_rn(v.w));
    *reinterpret_cast<uint2*>(g_x16 + i) = p;
}

// ---------------- kernel 2: gating (fp32, exact) ----------------
__global__ void k_gate(const float* __restrict__ x,
                       const float* __restrict__ Wg,
                       const float* __restrict__ bg) {
    int warp = (blockIdx.x * blockDim.x + threadIdx.x) >> 5;
    int lane = threadIdx.x & 31;
    if (warp >= T_TOK) return;
    const float* xr = x + (size_t)warp * DIM;
    float acc[NE];
#pragma unroll
    for (int e = 0; e < NE; e++) acc[e] = 0.0f;
    for (int d = lane; d < DIM; d += 32) {
        float xv = xr[d];
        const float4* wr = reinterpret_cast<const float4*>(Wg + d * NE);
        float4 w0 = wr[0], w1 = wr[1];
        acc[0] = fmaf(xv, w0.x, acc[0]); acc[1] = fmaf(xv, w0.y, acc[1]);
        acc[2] = fmaf(xv, w0.z, acc[2]); acc[3] = fmaf(xv, w0.w, acc[3]);
        acc[4] = fmaf(xv, w1.x, acc[4]); acc[5] = fmaf(xv, w1.y, acc[5]);
        acc[6] = fmaf(xv, w1.z, acc[6]); acc[7] = fmaf(xv, w1.w, acc[7]);
    }
#pragma unroll
    for (int off = 16; off; off >>= 1)
#pragma unroll
        for (int e = 0; e < NE; e++)
            acc[e] += __shfl_xor_sync(0xffffffffu, acc[e], off);
    if (lane == 0) {
        float l[NE], m = -1e30f;
#pragma unroll
        for (int e = 0; e < NE; e++) { l[e] = (acc[e] + bg[e]) / TEMPR; m = fmaxf(m, l[e]); }
        float p[NE], s = 0.0f;
#pragma unroll
        for (int e = 0; e < NE; e++) { p[e] = expf(l[e] - m); s += p[e]; }
        float inv_s = 1.0f / s;
#pragma unroll
        for (int e = 0; e < NE; e++) p[e] *= inv_s;
        int a0 = 0;
#pragma unroll
        for (int e = 1; e < NE; e++) if (p[e] > p[a0]) a0 = e;
        int a1 = -1;
#pragma unroll
        for (int e = 0; e < NE; e++) {
            if (e == a0) continue;
            if (a1 < 0 || p[e] > p[a1]) a1 = e;
        }
        float v0 = p[a0], v1 = p[a1];
        float inv = 1.0f / (v0 + v1 + EPSG);
        int pos0 = atomicAdd(&g_cnt[a0], 1);
        g_bucket[a0][pos0] = warp * 2;
        g_gate[warp * 2] = v0 * inv;
        int pos1 = atomicAdd(&g_cnt[a1], 1);
        g_bucket[a1][pos1] = warp * 2 + 1;
        g_gate[warp * 2 + 1] = v1 * inv;
    }
}

// ---------------- kernel 3: transpose weights to fp16 ----------------
template<int WSEL>
__global__ void k_tw(const float* __restrict__ W) {
    constexpr int Kd = (WSEL == 1) ? DIM : HID;
    constexpr int Nd = (WSEL == 1) ? HID : DIM;
    __half* Th = (WSEL == 1) ? g_w1 : g_w2;
    if (WSEL == 1 && blockIdx.x == 0 && blockIdx.y == 0 && blockIdx.z == 0 &&
        threadIdx.x == 0 && threadIdx.y == 0) {
        int s = 0;
#pragma unroll
        for (int e = 0; e < NE; e++) { g_base[e] = s; s += g_cnt[e]; }
    }
    __shared__ float t[32][33];
    const int e = blockIdx.z;
    const float* Wp = W + (size_t)e * Kd * Nd;
    const int n0 = blockIdx.x * 32, k0 = blockIdx.y * 32;
#pragma unroll
    for (int r = threadIdx.y; r < 32; r += 8)
        t[r][threadIdx.x] = Wp[(size_t)(k0 + r) * Nd + n0 + threadIdx.x];
    __syncthreads();
    __half* The = Th + (size_t)e * Nd * Kd;
    const int tid = threadIdx.y * 32 + threadIdx.x;
#pragma unroll
    for (int pass = 0; pass < 2; pass++) {
        int id = tid + pass * 256;
        int r = id >> 4;
        int q = id & 15;
        __half h0 = __float2half_rn(t[2 * q][r]);
        __half h1 = __float2half_rn(t[2 * q + 1][r]);
        size_t o = (size_t)(n0 + r) * Kd + k0 + 2 * q;
        *reinterpret_cast<uint32_t*>(The + o) = pack_h16(h0, h1);
    }
}

// ---------------- kernel 4: HMMA grouped GEMM (fp16), 2 CTAs/SM, 3-stage ring ----------------
// 192 threads, 6 warps: 3M x 2N warp grid, 32x64 warp tiles. BK=64.
template<int KTOT, int NTOT, int MODE>
__global__ __launch_bounds__(NTHR, 2) void k_gemm(const float* __restrict__ bias) {
    const int e = blockIdx.z;
    const int cnt = g_cnt[e];
    const int mb = blockIdx.x * BM;
    if (mb >= cnt) return;
    const int nb = blockIdx.y * BN;
    const int hbase = g_base[e];

    extern __shared__ __align__(128) char dsm[];
    __shared__ int s_row[BM];
    __shared__ int s_aid[BM];

    const int tid = threadIdx.x;
    const int lane = tid & 31;
    const int warp = tid >> 5;

    if (tid < BM) {
        int r = mb + tid;
        int aid = (r < cnt) ? g_bucket[e][r] : -1;
        s_aid[tid] = aid;
        if constexpr (MODE == 1)
            s_row[tid] = (aid >= 0) ? (aid >> 1) : 0;
        else
            s_row[tid] = hbase + ((r < cnt) ? r : 0);
    }
    __syncthreads();

    const __half *A_g, *B_g;
    if constexpr (MODE == 1) {
        A_g = g_x16;
        B_g = g_w1 + (size_t)e * NTOT * KTOT;
    } else {
        A_g = g_h16;
        B_g = g_w2 + (size_t)e * NTOT * KTOT;
    }

    const uint32_t smem0 = smem_u32(dsm);
    constexpr int NC = KTOT / BK;

    // ---- loader precompute ----
    uint32_t aGo[4], aSo[4];
#pragma unroll
    for (int it = 0; it < 4; it++) {
        int i = tid + it * NTHR;
        int row = i >> 3;
        uint32_t cb = (uint32_t)((i & 7) * 16);
        aGo[it] = (uint32_t)s_row[row] * (KTOT * 2) + cb;
        aSo[it] = (uint32_t)(row * 128) + (cb ^ (uint32_t)((row & 7) * 16));
    }
    const int br0 = tid >> 3;
    const uint32_t bcb = (uint32_t)((tid & 7) * 16);
    const uint32_t bSo0 = (uint32_t)(br0 * 128) + (bcb ^ (uint32_t)((br0 & 7) * 16));
    const uint32_t bGo0 = (uint32_t)(nb + br0) * (uint32_t)(KTOT * 2) + bcb;

    auto load_stage = [&](int c) {
        const uint32_t kk2 = (uint32_t)(c * BK * 2);
        const uint32_t st = smem0 + (uint32_t)(c % NSTAGE) * STAGE;
#pragma unroll
        for (int it = 0; it < 4; it++)
            cp16(st + OFF_A + aSo[it], (const char*)A_g + aGo[it] + kk2);
#pragma unroll
        for (int it = 0; it < 6; it++) {
            if (it < 5 || tid < 64) {
                uint32_t go = bGo0 + (uint32_t)(it * 24 * KTOT * 2) + kk2;
                uint32_t so = bSo0 + 3072u * (uint32_t)it;
                cp16(st + OFF_B + so, (const char*)B_g + go);
            }
        }
        cp_commit();
    };

    // ---- fragment addresses ----
    const int wm = warp >> 1;          // 3 warps over M (32 rows)
    const int wn = warp & 1;           // 2 warps over N (64 cols)
    uint32_t aOff[2], aX[2];
#pragma unroll
    for (int mt = 0; mt < 2; mt++) {
        int r = wm * 32 + mt * 16 + (lane & 15);
        aOff[mt] = (uint32_t)(r * 128);
        aX[mt] = (uint32_t)((r & 7) * 16);
    }
    const uint32_t aHiCb = (uint32_t)((lane >> 4) * 16);
    uint32_t bOff[4], bX[4];
#pragma unroll
    for (int np = 0; np < 4; np++) {
        int r = wn * 64 + np * 16 + (lane & 7) + ((lane >> 4) << 3);
        bOff[np] = (uint32_t)(r * 128);
        bX[np] = (uint32_t)((r & 7) * 16);
    }
    const uint32_t bHiCb = (uint32_t)(((lane >> 3) & 1) * 16);

    float acc[2][8][4];
#pragma unroll
    for (int mt = 0; mt < 2; mt++)
#pragma unroll
        for (int nt = 0; nt < 8; nt++)
#pragma unroll
            for (int q = 0; q < 4; q++) acc[mt][nt][q] = 0.0f;

    load_stage(0);
    load_stage(1);

    for (int c = 0; c < NC; c++) {
        if (c == NC - 1) cp_wait0(); else cp_wait1();
        __syncthreads();   // publishes stage c; all threads past compute c-1, so buffer (c+2)%3 is free
        if (c + 2 < NC) load_stage(c + 2);
        const uint32_t st = smem0 + (uint32_t)(c % NSTAGE) * STAGE;
#pragma unroll
        for (int ks = 0; ks < 4; ks++) {
            const uint32_t kcb = (uint32_t)(ks * 32);
            uint32_t a_f[2][4];
#pragma unroll
            for (int mt = 0; mt < 2; mt++) {
                uint32_t cb = kcb + aHiCb;
                uint32_t so = aOff[mt] + (cb ^ aX[mt]);
                ldm_x4(a_f[mt], st + OFF_A + so);
            }
#pragma unroll
            for (int np = 0; np < 4; np++) {
                uint32_t cb = kcb + bHiCb;
                uint32_t so = bOff[np] + (cb ^ bX[np]);
                uint32_t rh[4];
                ldm_x4(rh, st + OFF_B + so);
                mma_fp16(acc[0][2 * np],     a_f[0], rh);
                mma_fp16(acc[1][2 * np],     a_f[1], rh);
                mma_fp16(acc[0][2 * np + 1], a_f[0], rh + 2);
                mma_fp16(acc[1][2 * np + 1], a_f[1], rh + 2);
            }
        }
    }

    // ---- epilogue ----
    const int gid = lane >> 2, tig = lane & 3;
    const float* be = bias + (size_t)e * NTOT + nb;
#pragma unroll
    for (int mt = 0; mt < 2; mt++) {
        const int rA = wm * 32 + mt * 16 + gid;
        const int rB = rA + 8;
        const int aidA = s_aid[rA], aidB = s_aid[rB];
#pragma unroll
        for (int nt = 0; nt < 8; nt++) {
            const int cl = wn * 64 + nt * 8 + 2 * tig;
            const float b0 = be[cl], b1 = be[cl + 1];
            if constexpr (MODE == 1) {
                if (aidA >= 0) {
                    float g0 = gelu_exact(acc[mt][nt][0] + b0);
                    float g1 = gelu_exact(acc[mt][nt][1] + b1);
                    size_t o = (size_t)(hbase + mb + rA) * HID + nb + cl;
                    *reinterpret_cast<uint32_t*>(g_h16 + o) =
                        pack_h16(__float2half_rn(g0), __float2half_rn(g1));
                }
                if (aidB >= 0) {
                    float g0 = gelu_exact(acc[mt][nt][2] + b0);
                    float g1 = gelu_exact(acc[mt][nt][3] + b1);
                    size_t o = (size_t)(hbase + mb + rB) * HID + nb + cl;
                    *reinterpret_cast<uint32_t*>(g_h16 + o) =
                        pack_h16(__float2half_rn(g0), __float2half_rn(g1));
                }
            } else {
                if (aidA >= 0) {
                    float gate = g_gate[aidA];
                    float2 v;
                    v.x = gate * (acc[mt][nt][0] + b0);
                    v.y = gate * (acc[mt][nt][1] + b1);
                    *reinterpret_cast<float2*>(g_y + (size_t)aidA * DIM + nb + cl) = v;
                }
                if (aidB >= 0) {
                    float gate = g_gate[aidB];
                    float2 v;
                    v.x = gate * (acc[mt][nt][2] + b0);
                    v.y = gate * (acc[mt][nt][3] + b1);
                    *reinterpret_cast<float2*>(g_y + (size_t)aidB * DIM + nb + cl) = v;
                }
            }
        }
    }
}

// ---------------- kernel 5: combine ----------------
__global__ void k_combine(float* __restrict__ out) {
    size_t i = (size_t)blockIdx.x * blockDim.x + threadIdx.x;
    const size_t total4 = (size_t)T_TOK * DIM / 4;
    if (i >= total4) return;
    size_t t = i / (DIM / 4);
    size_t d4 = i % (DIM / 4);
    const float4* Y = reinterpret_cast<const float4*>(g_y);
    float4 a = Y[(2 * t) * (DIM / 4) + d4];
    float4 b = Y[(2 * t + 1) * (DIM / 4) + d4];
    float4 r;
    r.x = a.x + b.x; r.y = a.y + b.y; r.z = a.z + b.z; r.w = a.w + b.w;
    reinterpret_cast<float4*>(out)[i] = r;
}

// ---------------- launch ----------------
extern "C" void kernel_launch(void* const* d_in, const int* in_sizes, int n_in,
                              void* d_out, int out_size) {
    const float* x  = (const float*)d_in[0];
    const float* Wg = (const float*)d_in[1];
    const float* bg = (const float*)d_in[2];
    const float* W1 = (const float*)d_in[3];
    const float* b1 = (const float*)d_in[4];
    const float* W2 = (const float*)d_in[5];
    const float* b2 = (const float*)d_in[6];
    float* out = (float*)d_out;

    cudaFuncSetAttribute(k_gemm<DIM, HID, 1>, cudaFuncAttributeMaxDynamicSharedMemorySize, SMEM_DYN);
    cudaFuncSetAttribute(k_gemm<HID, DIM, 2>, cudaFuncAttributeMaxDynamicSharedMemorySize, SMEM_DYN);

    const int MBLK = (T_TOK + BM - 1) / BM;   // 86

    // gemm1 stays the 4th launch (ncu profiled slot)
    k_split_x<<<(T_TOK * DIM / 4 + 255) / 256, 256>>>(x);          // 1 (zeroes g_cnt)
    k_gate<<<T_TOK / 8, 256>>>(x, Wg, bg);                          // 2
    k_tw<1><<<dim3(HID / 32, DIM / 32, NE), dim3(32, 8)>>>(W1);     // 3 (computes g_base)
    k_gemm<DIM, HID, 1><<<dim3(MBLK, HID / BN, NE), NTHR, SMEM_DYN>>>(b1);   // 4 <- profiled
    k_tw<2><<<dim3(DIM / 32, HID / 32, NE), dim3(32, 8)>>>(W2);     // 5
    k_gemm<HID, DIM, 2><<<dim3(MBLK, DIM / BN, NE), NTHR, SMEM_DYN>>>(b2);   // 6
    k_combine<<<(T_TOK * DIM / 4 + 255) / 256, 256>>>(out);         // 7
}

// round 15
// speedup vs baseline: 1.0264x; 1.0264x over previous
#include <cuda_runtime.h>
#include <cuda_fp16.h>
#include <math.h>
#include <stdint.h>

#define T_TOK 8192
#define DIM   1024
#define HID   2048
#define NE    8
#define TEMPR 5.0f
#define EPSG  1e-9f

#define BM 96
#define BN 128
#define BK 64
#define NTHR 192
// stage layout (128B rows): A = 96x128B; B = 128x128B
#define OFF_A  0
#define OFF_B  (BM*128)                 // 12288
#define STAGE  (BM*128 + BN*128)        // 28672
#define SMEM_DYN (2*STAGE)              // 57344 (x2 CTAs/SM)

// ---------------- scratch ----------------
__device__ int   g_cnt[NE];
__device__ int   g_base[NE];
__device__ int   g_bucket[NE][T_TOK];
__device__ float g_gate[2 * T_TOK];
__device__ __half g_x16[(size_t)T_TOK * DIM];
__device__ __half g_w1[(size_t)NE * DIM * HID];    // transposed [e][h][d], fp16
__device__ __half g_w2[(size_t)NE * HID * DIM];    // transposed [e][d][h], fp16
__device__ __half g_h16[(size_t)2 * T_TOK * HID];  // contiguous per expert

// ---------------- helpers ----------------
__device__ __forceinline__ uint32_t smem_u32(const void* p) {
    uint32_t r;
    asm("{ .reg .u64 t; cvta.to.shared.u64 t, %1; cvt.u32.u64 %0, t; }" : "=r"(r) : "l"(p));
    return r;
}
__device__ __forceinline__ void cp16(uint32_t dst, const void* src) {
    asm volatile("cp.async.cg.shared.global [%0], [%1], 16;" :: "r"(dst), "l"(src));
}
__device__ __forceinline__ void cp_commit() {
    asm volatile("cp.async.commit_group;" ::: "memory");
}
__device__ __forceinline__ void cp_wait0() {
    asm volatile("cp.async.wait_group 0;" ::: "memory");
}
__device__ __forceinline__ void ldm_x4(uint32_t* r, uint32_t addr) {
    asm volatile("ldmatrix.sync.aligned.m8n8.x4.shared.b16 {%0,%1,%2,%3}, [%4];"
                 : "=r"(r[0]), "=r"(r[1]), "=r"(r[2]), "=r"(r[3]) : "r"(addr));
}
__device__ __forceinline__ void mma_fp16(float* d, const uint32_t* a, const uint32_t* b) {
    asm volatile(
        "mma.sync.aligned.m16n8k16.row.col.f32.f16.f16.f32 "
        "{%0,%1,%2,%3}, {%4,%5,%6,%7}, {%8,%9}, {%0,%1,%2,%3};"
        : "+f"(d[0]), "+f"(d[1]), "+f"(d[2]), "+f"(d[3])
        : "r"(a[0]), "r"(a[1]), "r"(a[2]), "r"(a[3]), "r"(b[0]), "r"(b[1]));
}
__device__ __forceinline__ float gelu_exact(float v) {
    return 0.5f * v * (1.0f + erff(v * 0.70710678118654752f));
}
__device__ __forceinline__ uint32_t pack_h16(__half a, __half b) {
    return ((uint32_t)__half_as_ushort(b) << 16) | (uint32_t)__half_as_ushort(a);
}

// ---------------- kernel 1: x -> fp16; zero g_cnt; zero out ----------------
__global__ void k_split_x(const float* __restrict__ x, float* __restrict__ out) {
    if (blockIdx.x == 0 && threadIdx.x < NE) g_cnt[threadIdx.x] = 0;
    size_t i = ((size_t)blockIdx.x * blockDim.x + threadIdx.x) * 4;
    if (i >= (size_t)T_TOK * DIM) return;
    float4 v = *reinterpret_cast<const float4*>(x + i);
    uint2 p;
    p.x = pack_h16(__float2half_rn(v.x), __float2half_rn(v.y));
    p.y = pack_h16(__float2half_rn(v.z), __float2half_rn(v.w));
    *reinterpret_cast<uint2*>(g_x16 + i) = p;
    *reinterpret_cast<float4*>(out + i) = make_float4(0.f, 0.f, 0.f, 0.f);
}

// ---------------- kernel 2: gating (fp32, exact) ----------------
__global__ void k_gate(const float* __restrict__ x,
                       const float* __restrict__ Wg,
                       const float* __restrict__ bg) {
    int warp = (blockIdx.x * blockDim.x + threadIdx.x) >> 5;
    int lane = threadIdx.x & 31;
    if (warp >= T_TOK) return;
    const float* xr = x + (size_t)warp * DIM;
    float acc[NE];
#pragma unroll
    for (int e = 0; e < NE; e++) acc[e] = 0.0f;
    for (int d = lane; d < DIM; d += 32) {
        float xv = xr[d];
        const float4* wr = reinterpret_cast<const float4*>(Wg + d * NE);
        float4 w0 = wr[0], w1 = wr[1];
        acc[0] = fmaf(xv, w0.x, acc[0]); acc[1] = fmaf(xv, w0.y, acc[1]);
        acc[2] = fmaf(xv, w0.z, acc[2]); acc[3] = fmaf(xv, w0.w, acc[3]);
        acc[4] = fmaf(xv, w1.x, acc[4]); acc[5] = fmaf(xv, w1.y, acc[5]);
        acc[6] = fmaf(xv, w1.z, acc[6]); acc[7] = fmaf(xv, w1.w, acc[7]);
    }
#pragma unroll
    for (int off = 16; off; off >>= 1)
#pragma unroll
        for (int e = 0; e < NE; e++)
            acc[e] += __shfl_xor_sync(0xffffffffu, acc[e], off);
    if (lane == 0) {
        float l[NE], m = -1e30f;
#pragma unroll
        for (int e = 0; e < NE; e++) { l[e] = (acc[e] + bg[e]) / TEMPR; m = fmaxf(m, l[e]); }
        float p[NE], s = 0.0f;
#pragma unroll
        for (int e = 0; e < NE; e++) { p[e] = expf(l[e] - m); s += p[e]; }
        float inv_s = 1.0f / s;
#pragma unroll
        for (int e = 0; e < NE; e++) p[e] *= inv_s;
        int a0 = 0;
#pragma unroll
        for (int e = 1; e < NE; e++) if (p[e] > p[a0]) a0 = e;
        int a1 = -1;
#pragma unroll
        for (int e = 0; e < NE; e++) {
            if (e == a0) continue;
            if (a1 < 0 || p[e] > p[a1]) a1 = e;
        }
        float v0 = p[a0], v1 = p[a1];
        float inv = 1.0f / (v0 + v1 + EPSG);
        int pos0 = atomicAdd(&g_cnt[a0], 1);
        g_bucket[a0][pos0] = warp * 2;
        g_gate[warp * 2] = v0 * inv;
        int pos1 = atomicAdd(&g_cnt[a1], 1);
        g_bucket[a1][pos1] = warp * 2 + 1;
        g_gate[warp * 2 + 1] = v1 * inv;
    }
}

// ---------------- kernel 3: transpose weights to fp16 (32n x 64k tiles, coalesced) ----------------
template<int WSEL>
__global__ void k_tw(const float* __restrict__ W) {
    constexpr int Kd = (WSEL == 1) ? DIM : HID;
    constexpr int Nd = (WSEL == 1) ? HID : DIM;
    __half* Th = (WSEL == 1) ? g_w1 : g_w2;
    if (WSEL == 1 && blockIdx.x == 0 && blockIdx.y == 0 && blockIdx.z == 0 &&
        threadIdx.x == 0 && threadIdx.y == 0) {
        int s = 0;
#pragma unroll
        for (int e = 0; e < NE; e++) { g_base[e] = s; s += g_cnt[e]; }
    }
    __shared__ float t[64][33];
    const int e = blockIdx.z;
    const float* Wp = W + (size_t)e * Kd * Nd;
    const int n0 = blockIdx.x * 32, k0 = blockIdx.y * 64;
#pragma unroll
    for (int r = threadIdx.y; r < 64; r += 8)
        t[r][threadIdx.x] = Wp[(size_t)(k0 + r) * Nd + n0 + threadIdx.x];
    __syncthreads();
    __half* The = Th + (size_t)e * Nd * Kd;
    const int tid = threadIdx.y * 32 + threadIdx.x;
#pragma unroll
    for (int pass = 0; pass < 4; pass++) {
        int id = tid + pass * 256;          // 0..1023
        int r = id >> 5;                    // n-local 0..31
        int q = id & 31;                    // k-pair 0..31
        __half h0 = __float2half_rn(t[2 * q][r]);
        __half h1 = __float2half_rn(t[2 * q + 1][r]);
        size_t o = (size_t)(n0 + r) * Kd + k0 + 2 * q;
        *reinterpret_cast<uint32_t*>(The + o) = pack_h16(h0, h1);
    }
}

// ---------------- kernel 4: HMMA grouped GEMM (fp16), 2 CTAs/SM ----------------
// 192 threads, 6 warps: 3M x 2N warp grid, 32x64 warp tiles. BK=64, 1 barrier/stage.
// MODE 1: -> g_h16 (gelu). MODE 2: atomicAdd into out (gate*(acc+bias)), deterministic.
template<int KTOT, int NTOT, int MODE>
__global__ __launch_bounds__(NTHR, 2) void k_gemm(const float* __restrict__ bias,
                                                  float* __restrict__ out) {
    const int e = blockIdx.z;
    const int cnt = g_cnt[e];
    const int mb = blockIdx.x * BM;
    if (mb >= cnt) return;
    const int nb = blockIdx.y * BN;
    const int hbase = g_base[e];

    extern __shared__ __align__(128) char dsm[];
    __shared__ int s_row[BM];
    __shared__ int s_aid[BM];

    const int tid = threadIdx.x;
    const int lane = tid & 31;
    const int warp = tid >> 5;

    if (tid < BM) {
        int r = mb + tid;
        int aid = (r < cnt) ? g_bucket[e][r] : -1;
        s_aid[tid] = aid;
        if constexpr (MODE == 1)
            s_row[tid] = (aid >= 0) ? (aid >> 1) : 0;
        else
            s_row[tid] = hbase + ((r < cnt) ? r : 0);
    }
    __syncthreads();

    const __half *A_g, *B_g;
    if constexpr (MODE == 1) {
        A_g = g_x16;
        B_g = g_w1 + (size_t)e * NTOT * KTOT;
    } else {
        A_g = g_h16;
        B_g = g_w2 + (size_t)e * NTOT * KTOT;
    }

    const uint32_t smem0 = smem_u32(dsm);
    constexpr int NC = KTOT / BK;

    // ---- loader precompute ----
    uint32_t aGo[4], aSo[4];
#pragma unroll
    for (int it = 0; it < 4; it++) {
        int i = tid + it * NTHR;
        int row = i >> 3;
        uint32_t cb = (uint32_t)((i & 7) * 16);
        aGo[it] = (uint32_t)s_row[row] * (KTOT * 2) + cb;
        aSo[it] = (uint32_t)(row * 128) + (cb ^ (uint32_t)((row & 7) * 16));
    }
    const int br0 = tid >> 3;
    const uint32_t bcb = (uint32_t)((tid & 7) * 16);
    const uint32_t bSo0 = (uint32_t)(br0 * 128) + (bcb ^ (uint32_t)((br0 & 7) * 16));
    const uint32_t bGo0 = (uint32_t)(nb + br0) * (uint32_t)(KTOT * 2) + bcb;

    auto load_stage = [&](int c) {
        const uint32_t kk2 = (uint32_t)(c * BK * 2);
        const uint32_t st = smem0 + (c & 1) * STAGE;
#pragma unroll
        for (int it = 0; it < 4; it++)
            cp16(st + OFF_A + aSo[it], (const char*)A_g + aGo[it] + kk2);
#pragma unroll
        for (int it = 0; it < 6; it++) {
            if (it < 5 || tid < 64) {
                uint32_t go = bGo0 + (uint32_t)(it * 24 * KTOT * 2) + kk2;
                uint32_t so = bSo0 + 3072u * (uint32_t)it;
                cp16(st + OFF_B + so, (const char*)B_g + go);
            }
        }
        cp_commit();
    };

    // ---- fragment addresses ----
    const int wm = warp >> 1;          // 3 warps over M (32 rows)
    const int wn = warp & 1;           // 2 warps over N (64 cols)
    uint32_t aOff[2], aX[2];
#pragma unroll
    for (int mt = 0; mt < 2; mt++) {
        int r = wm * 32 + mt * 16 + (lane & 15);
        aOff[mt] = (uint32_t)(r * 128);
        aX[mt] = (uint32_t)((r & 7) * 16);
    }
    const uint32_t aHiCb = (uint32_t)((lane >> 4) * 16);
    uint32_t bOff[4], bX[4];
#pragma unroll
    for (int np = 0; np < 4; np++) {
        int r = wn * 64 + np * 16 + (lane & 7) + ((lane >> 4) << 3);
        bOff[np] = (uint32_t)(r * 128);
        bX[np] = (uint32_t)((r & 7) * 16);
    }
    const uint32_t bHiCb = (uint32_t)(((lane >> 3) & 1) * 16);

    float acc[2][8][4];
#pragma unroll
    for (int mt = 0; mt < 2; mt++)
#pragma unroll
        for (int nt = 0; nt < 8; nt++)
#pragma unroll
            for (int q = 0; q < 4; q++) acc[mt][nt][q] = 0.0f;

    load_stage(0);

    for (int c = 0; c < NC; c++) {
        cp_wait0();
        __syncthreads();
        if (c + 1 < NC) load_stage(c + 1);
        const uint32_t st = smem0 + (c & 1) * STAGE;
#pragma unroll
        for (int ks = 0; ks < 4; ks++) {
            const uint32_t kcb = (uint32_t)(ks * 32);
            uint32_t a_f[2][4];
#pragma unroll
            for (int mt = 0; mt < 2; mt++) {
                uint32_t cb = kcb + aHiCb;
                uint32_t so = aOff[mt] + (cb ^ aX[mt]);
                ldm_x4(a_f[mt], st + OFF_A + so);
            }
#pragma unroll
            for (int np = 0; np < 4; np++) {
                uint32_t cb = kcb + bHiCb;
                uint32_t so = bOff[np] + (cb ^ bX[np]);
                uint32_t rh[4];
                ldm_x4(rh, st + OFF_B + so);
                mma_fp16(acc[0][2 * np],     a_f[0], rh);
                mma_fp16(acc[1][2 * np],     a_f[1], rh);
                mma_fp16(acc[0][2 * np + 1], a_f[0], rh + 2);
                mma_fp16(acc[1][2 * np + 1], a_f[1], rh + 2);
            }
        }
    }

    // ---- epilogue ----
    const int gid = lane >> 2, tig = lane & 3;
    const float* be = bias + (size_t)e * NTOT + nb;
#pragma unroll
    for (int mt = 0; mt < 2; mt++) {
        const int rA = wm * 32 + mt * 16 + gid;
        const int rB = rA + 8;
        const int aidA = s_aid[rA], aidB = s_aid[rB];
#pragma unroll
        for (int nt = 0; nt < 8; nt++) {
            const int cl = wn * 64 + nt * 8 + 2 * tig;
            const float b0 = be[cl], b1 = be[cl + 1];
            if constexpr (MODE == 1) {
                if (aidA >= 0) {
                    float g0 = gelu_exact(acc[mt][nt][0] + b0);
                    float g1 = gelu_exact(acc[mt][nt][1] + b1);
                    size_t o = (size_t)(hbase + mb + rA) * HID + nb + cl;
                    *reinterpret_cast<uint32_t*>(g_h16 + o) =
                        pack_h16(__float2half_rn(g0), __float2half_rn(g1));
                }
                if (aidB >= 0) {
                    float g0 = gelu_exact(acc[mt][nt][2] + b0);
                    float g1 = gelu_exact(acc[mt][nt][3] + b1);
                    size_t o = (size_t)(hbase + mb + rB) * HID + nb + cl;
                    *reinterpret_cast<uint32_t*>(g_h16 + o) =
                        pack_h16(__float2half_rn(g0), __float2half_rn(g1));
                }
            } else {
                if (aidA >= 0) {
                    float gate = g_gate[aidA];
                    float* op = out + (size_t)(aidA >> 1) * DIM + nb + cl;
                    atomicAdd(op,     gate * (acc[mt][nt][0] + b0));
                    atomicAdd(op + 1, gate * (acc[mt][nt][1] + b1));
                }
                if (aidB >= 0) {
                    float gate = g_gate[aidB];
                    float* op = out + (size_t)(aidB >> 1) * DIM + nb + cl;
                    atomicAdd(op,     gate * (acc[mt][nt][2] + b0));
                    atomicAdd(op + 1, gate * (acc[mt][nt][3] + b1));
                }
            }
        }
    }
}

// ---------------- launch ----------------
extern "C" void kernel_launch(void* const* d_in, const int* in_sizes, int n_in,
                              void* d_out, int out_size) {
    const float* x  = (const float*)d_in[0];
    const float* Wg = (const float*)d_in[1];
    const float* bg = (const float*)d_in[2];
    const float* W1 = (const float*)d_in[3];
    const float* b1 = (const float*)d_in[4];
    const float* W2 = (const float*)d_in[5];
    const float* b2 = (const float*)d_in[6];
    float* out = (float*)d_out;

    cudaFuncSetAttribute(k_gemm<DIM, HID, 1>, cudaFuncAttributeMaxDynamicSharedMemorySize, SMEM_DYN);
    cudaFuncSetAttribute(k_gemm<HID, DIM, 2>, cudaFuncAttributeMaxDynamicSharedMemorySize, SMEM_DYN);

    const int MBLK = (T_TOK + BM - 1) / BM;   // 86

    // gemm1 stays the 4th launch (ncu profiled slot)
    k_split_x<<<(T_TOK * DIM / 4 + 255) / 256, 256>>>(x, out);     // 1 (zeroes g_cnt + out)
    k_gate<<<T_TOK / 8, 256>>>(x, Wg, bg);                          // 2
    k_tw<1><<<dim3(HID / 32, DIM / 64, NE), dim3(32, 8)>>>(W1);     // 3 (computes g_base)
    k_gemm<DIM, HID, 1><<<dim3(MBLK, HID / BN, NE), NTHR, SMEM_DYN>>>(b1, out); // 4 <- profiled
    k_tw<2><<<dim3(DIM / 32, HID / 64, NE), dim3(32, 8)>>>(W2);     // 5
    k_gemm<HID, DIM, 2><<<dim3(MBLK, DIM / BN, NE), NTHR, SMEM_DYN>>>(b2, out); // 6
}

// round 16
// speedup vs baseline: 1.1280x; 1.0989x over previous
#include <cuda_runtime.h>
#include <cuda_fp16.h>
#include <math.h>
#include <stdint.h>

#define T_TOK 8192
#define DIM   1024
#define HID   2048
#define NE    8
#define TEMPR 5.0f
#define EPSG  1e-9f

#define BM 96
#define BN 128
#define BK 64
#define NTHR 192
// stage layout (128B rows): A = 96x128B; B = 128x128B
#define OFF_A  0
#define OFF_B  (BM*128)                 // 12288
#define STAGE  (BM*128 + BN*128)        // 28672
#define SMEM_DYN (2*STAGE)              // 57344 (x2 CTAs/SM)

// prep kernel block ranges
#define PREP_SPLIT_BLKS 8192
#define PREP_GATE_BLKS  1024
#define PREP_TW1_BLKS   (64*16*8)       // 8192  (grid 64 x 16 x 8)
#define PREP_TW2_BLKS   (32*32*8)       // 8192  (grid 32 x 32 x 8)
#define PREP_TOTAL (PREP_SPLIT_BLKS + PREP_GATE_BLKS + PREP_TW1_BLKS + PREP_TW2_BLKS)

// ---------------- scratch ----------------
__device__ int   g_cnt[NE];
__device__ int   g_bucket[NE][T_TOK];
__device__ float g_gate[2 * T_TOK];
__device__ __half g_x16[(size_t)T_TOK * DIM];
__device__ __half g_w1[(size_t)NE * DIM * HID];    // transposed [e][h][d], fp16
__device__ __half g_w2[(size_t)NE * HID * DIM];    // transposed [e][d][h], fp16
__device__ __half g_h16[(size_t)2 * T_TOK * HID];  // contiguous per expert

// ---------------- helpers ----------------
__device__ __forceinline__ uint32_t smem_u32(const void* p) {
    uint32_t r;
    asm("{ .reg .u64 t; cvta.to.shared.u64 t, %1; cvt.u32.u64 %0, t; }" : "=r"(r) : "l"(p));
    return r;
}
__device__ __forceinline__ void cp16(uint32_t dst, const void* src) {
    asm volatile("cp.async.cg.shared.global [%0], [%1], 16;" :: "r"(dst), "l"(src));
}
__device__ __forceinline__ void cp_commit() {
    asm volatile("cp.async.commit_group;" ::: "memory");
}
__device__ __forceinline__ void cp_wait0() {
    asm volatile("cp.async.wait_group 0;" ::: "memory");
}
__device__ __forceinline__ void ldm_x4(uint32_t* r, uint32_t addr) {
    asm volatile("ldmatrix.sync.aligned.m8n8.x4.shared.b16 {%0,%1,%2,%3}, [%4];"
                 : "=r"(r[0]), "=r"(r[1]), "=r"(r[2]), "=r"(r[3]) : "r"(addr));
}
__device__ __forceinline__ void mma_fp16(float* d, const uint32_t* a, const uint32_t* b) {
    asm volatile(
        "mma.sync.aligned.m16n8k16.row.col.f32.f16.f16.f32 "
        "{%0,%1,%2,%3}, {%4,%5,%6,%7}, {%8,%9}, {%0,%1,%2,%3};"
        : "+f"(d[0]), "+f"(d[1]), "+f"(d[2]), "+f"(d[3])
        : "r"(a[0]), "r"(a[1]), "r"(a[2]), "r"(a[3]), "r"(b[0]), "r"(b[1]));
}
__device__ __forceinline__ float gelu_exact(float v) {
    return 0.5f * v * (1.0f + erff(v * 0.70710678118654752f));
}
__device__ __forceinline__ uint32_t pack_h16(__half a, __half b) {
    return ((uint32_t)__half_as_ushort(b) << 16) | (uint32_t)__half_as_ushort(a);
}
__device__ __forceinline__ void red_add_f32x2(float* addr, float x, float y) {
    asm volatile("red.global.add.v2.f32 [%0], {%1, %2};" :: "l"(addr), "f"(x), "f"(y) : "memory");
}

// ---------------- kernel 1: fused prep (split_x + gate + tw1 + tw2) ----------------
// All four roles are mutually independent; one launch fills the chip.
template<int WSEL>
__device__ void tw_body(const float* __restrict__ W, int bx, int by, int e, int tid) {
    constexpr int Kd = (WSEL == 1) ? DIM : HID;
    constexpr int Nd = (WSEL == 1) ? HID : DIM;
    __half* Th = (WSEL == 1) ? g_w1 : g_w2;
    __shared__ float t[64][33];
    const float* Wp = W + (size_t)e * Kd * Nd;
    const int n0 = bx * 32, k0 = by * 64;
    const int tx = tid & 31, ty = tid >> 5;
#pragma unroll
    for (int r = ty; r < 64; r += 8)
        t[r][tx] = Wp[(size_t)(k0 + r) * Nd + n0 + tx];
    __syncthreads();
    __half* The = Th + (size_t)e * Nd * Kd;
#pragma unroll
    for (int pass = 0; pass < 4; pass++) {
        int id = tid + pass * 256;
        int r = id >> 5;
        int q = id & 31;
        __half h0 = __float2half_rn(t[2 * q][r]);
        __half h1 = __float2half_rn(t[2 * q + 1][r]);
        size_t o = (size_t)(n0 + r) * Kd + k0 + 2 * q;
        *reinterpret_cast<uint32_t*>(The + o) = pack_h16(h0, h1);
    }
}

__global__ __launch_bounds__(256) void k_prep(const float* __restrict__ x,
                                              const float* __restrict__ Wg,
                                              const float* __restrict__ bg,
                                              const float* __restrict__ W1,
                                              const float* __restrict__ W2,
                                              float* __restrict__ out) {
    const int blk = blockIdx.x;
    const int tid = threadIdx.x;

    if (blk < PREP_SPLIT_BLKS) {
        // ---- role: x -> fp16, zero out, zero g_cnt ----
        if (blk == 0 && tid < NE) g_cnt[tid] = 0;
        size_t i = ((size_t)blk * 256 + tid) * 4;
        float4 v = *reinterpret_cast<const float4*>(x + i);
        uint2 p;
        p.x = pack_h16(__float2half_rn(v.x), __float2half_rn(v.y));
        p.y = pack_h16(__float2half_rn(v.z), __float2half_rn(v.w));
        *reinterpret_cast<uint2*>(g_x16 + i) = p;
        *reinterpret_cast<float4*>(out + i) = make_float4(0.f, 0.f, 0.f, 0.f);
        return;
    }
    if (blk < PREP_SPLIT_BLKS + PREP_GATE_BLKS) {
        // ---- role: gating (8 warps, 1 token each) ----
        const int gblk = blk - PREP_SPLIT_BLKS;
        const int token = gblk * 8 + (tid >> 5);
        const int lane = tid & 31;
        const float* xr = x + (size_t)token * DIM;
        float acc[NE];
#pragma unroll
        for (int e = 0; e < NE; e++) acc[e] = 0.0f;
        for (int d = lane; d < DIM; d += 32) {
            float xv = xr[d];
            const float4* wr = reinterpret_cast<const float4*>(Wg + d * NE);
            float4 w0 = wr[0], w1 = wr[1];
            acc[0] = fmaf(xv, w0.x, acc[0]); acc[1] = fmaf(xv, w0.y, acc[1]);
            acc[2] = fmaf(xv, w0.z, acc[2]); acc[3] = fmaf(xv, w0.w, acc[3]);
            acc[4] = fmaf(xv, w1.x, acc[4]); acc[5] = fmaf(xv, w1.y, acc[5]);
            acc[6] = fmaf(xv, w1.z, acc[6]); acc[7] = fmaf(xv, w1.w, acc[7]);
        }
#pragma unroll
        for (int off = 16; off; off >>= 1)
#pragma unroll
            for (int e = 0; e < NE; e++)
                acc[e] += __shfl_xor_sync(0xffffffffu, acc[e], off);
        if (lane == 0) {
            float l[NE], m = -1e30f;
#pragma unroll
            for (int e = 0; e < NE; e++) { l[e] = (acc[e] + bg[e]) / TEMPR; m = fmaxf(m, l[e]); }
            float p[NE], s = 0.0f;
#pragma unroll
            for (int e = 0; e < NE; e++) { p[e] = expf(l[e] - m); s += p[e]; }
            float inv_s = 1.0f / s;
#pragma unroll
            for (int e = 0; e < NE; e++) p[e] *= inv_s;
            int a0 = 0;
#pragma unroll
            for (int e = 1; e < NE; e++) if (p[e] > p[a0]) a0 = e;
            int a1 = -1;
#pragma unroll
            for (int e = 0; e < NE; e++) {
                if (e == a0) continue;
                if (a1 < 0 || p[e] > p[a1]) a1 = e;
            }
            float v0 = p[a0], v1 = p[a1];
            float inv = 1.0f / (v0 + v1 + EPSG);
            int pos0 = atomicAdd(&g_cnt[a0], 1);
            g_bucket[a0][pos0] = token * 2;
            g_gate[token * 2] = v0 * inv;
            int pos1 = atomicAdd(&g_cnt[a1], 1);
            g_bucket[a1][pos1] = token * 2 + 1;
            g_gate[token * 2 + 1] = v1 * inv;
        }
        return;
    }
    if (blk < PREP_SPLIT_BLKS + PREP_GATE_BLKS + PREP_TW1_BLKS) {
        // ---- role: W1 transpose+convert; grid (64, 16, 8) ----
        int idx = blk - PREP_SPLIT_BLKS - PREP_GATE_BLKS;
        int bx = idx % 64; idx /= 64;
        int by = idx % 16; idx /= 16;
        tw_body<1>(W1, bx, by, idx, tid);
        return;
    }
    {
        // ---- role: W2 transpose+convert; grid (32, 32, 8) ----
        int idx = blk - PREP_SPLIT_BLKS - PREP_GATE_BLKS - PREP_TW1_BLKS;
        int bx = idx % 32; idx /= 32;
        int by = idx % 32; idx /= 32;
        tw_body<2>(W2, bx, by, idx, tid);
    }
}

// ---------------- kernel 2: HMMA grouped GEMM (fp16), 2 CTAs/SM ----------------
// 192 threads, 6 warps: 3M x 2N warp grid, 32x64 warp tiles. BK=64, 1 barrier/stage.
// MODE 1: -> g_h16 (gelu). MODE 2: red.v2.f32 into out, deterministic value.
template<int KTOT, int NTOT, int MODE>
__global__ __launch_bounds__(NTHR, 2) void k_gemm(const float* __restrict__ bias,
                                                  float* __restrict__ out) {
    const int e = blockIdx.z;
    const int cnt = g_cnt[e];
    const int mb = blockIdx.x * BM;
    if (mb >= cnt) return;
    const int nb = blockIdx.y * BN;
    int hbase = 0;
#pragma unroll
    for (int i = 0; i < NE; i++) hbase += (i < e) ? g_cnt[i] : 0;

    extern __shared__ __align__(128) char dsm[];
    __shared__ int s_row[BM];
    __shared__ int s_aid[BM];

    const int tid = threadIdx.x;
    const int lane = tid & 31;
    const int warp = tid >> 5;

    if (tid < BM) {
        int r = mb + tid;
        int aid = (r < cnt) ? g_bucket[e][r] : -1;
        s_aid[tid] = aid;
        if constexpr (MODE == 1)
            s_row[tid] = (aid >= 0) ? (aid >> 1) : 0;
        else
            s_row[tid] = hbase + ((r < cnt) ? r : 0);
    }
    __syncthreads();

    const __half *A_g, *B_g;
    if constexpr (MODE == 1) {
        A_g = g_x16;
        B_g = g_w1 + (size_t)e * NTOT * KTOT;
    } else {
        A_g = g_h16;
        B_g = g_w2 + (size_t)e * NTOT * KTOT;
    }

    const uint32_t smem0 = smem_u32(dsm);
    constexpr int NC = KTOT / BK;

    // ---- loader precompute ----
    uint32_t aGo[4], aSo[4];
#pragma unroll
    for (int it = 0; it < 4; it++) {
        int i = tid + it * NTHR;
        int row = i >> 3;
        uint32_t cb = (uint32_t)((i & 7) * 16);
        aGo[it] = (uint32_t)s_row[row] * (KTOT * 2) + cb;
        aSo[it] = (uint32_t)(row * 128) + (cb ^ (uint32_t)((row & 7) * 16));
    }
    const int br0 = tid >> 3;
    const uint32_t bcb = (uint32_t)((tid & 7) * 16);
    const uint32_t bSo0 = (uint32_t)(br0 * 128) + (bcb ^ (uint32_t)((br0 & 7) * 16));
    const uint32_t bGo0 = (uint32_t)(nb + br0) * (uint32_t)(KTOT * 2) + bcb;

    auto load_stage = [&](int c) {
        const uint32_t kk2 = (uint32_t)(c * BK * 2);
        const uint32_t st = smem0 + (c & 1) * STAGE;
#pragma unroll
        for (int it = 0; it < 4; it++)
            cp16(st + OFF_A + aSo[it], (const char*)A_g + aGo[it] + kk2);
#pragma unroll
        for (int it = 0; it < 6; it++) {
            if (it < 5 || tid < 64) {
                uint32_t go = bGo0 + (uint32_t)(it * 24 * KTOT * 2) + kk2;
                uint32_t so = bSo0 + 3072u * (uint32_t)it;
                cp16(st + OFF_B + so, (const char*)B_g + go);
            }
        }
        cp_commit();
    };

    // ---- fragment addresses ----
    const int wm = warp >> 1;          // 3 warps over M (32 rows)
    const int wn = warp & 1;           // 2 warps over N (64 cols)
    uint32_t aOff[2], aX[2];
#pragma unroll
    for (int mt = 0; mt < 2; mt++) {
        int r = wm * 32 + mt * 16 + (lane & 15);
        aOff[mt] = (uint32_t)(r * 128);
        aX[mt] = (uint32_t)((r & 7) * 16);
    }
    const uint32_t aHiCb = (uint32_t)((lane >> 4) * 16);
    uint32_t bOff[4], bX[4];
#pragma unroll
    for (int np = 0; np < 4; np++) {
        int r = wn * 64 + np * 16 + (lane & 7) + ((lane >> 4) << 3);
        bOff[np] = (uint32_t)(r * 128);
        bX[np] = (uint32_t)((r & 7) * 16);
    }
    const uint32_t bHiCb = (uint32_t)(((lane >> 3) & 1) * 16);

    float acc[2][8][4];
#pragma unroll
    for (int mt = 0; mt < 2; mt++)
#pragma unroll
        for (int nt = 0; nt < 8; nt++)
#pragma unroll
            for (int q = 0; q < 4; q++) acc[mt][nt][q] = 0.0f;

    load_stage(0);

    for (int c = 0; c < NC; c++) {
        cp_wait0();
        __syncthreads();
        if (c + 1 < NC) load_stage(c + 1);
        const uint32_t st = smem0 + (c & 1) * STAGE;
#pragma unroll
        for (int ks = 0; ks < 4; ks++) {
            const uint32_t kcb = (uint32_t)(ks * 32);
            uint32_t a_f[2][4];
#pragma unroll
            for (int mt = 0; mt < 2; mt++) {
                uint32_t cb = kcb + aHiCb;
                uint32_t so = aOff[mt] + (cb ^ aX[mt]);
                ldm_x4(a_f[mt], st + OFF_A + so);
            }
#pragma unroll
            for (int np = 0; np < 4; np++) {
                uint32_t cb = kcb + bHiCb;
                uint32_t so = bOff[np] + (cb ^ bX[np]);
                uint32_t rh[4];
                ldm_x4(rh, st + OFF_B + so);
                mma_fp16(acc[0][2 * np],     a_f[0], rh);
                mma_fp16(acc[1][2 * np],     a_f[1], rh);
                mma_fp16(acc[0][2 * np + 1], a_f[0], rh + 2);
                mma_fp16(acc[1][2 * np + 1], a_f[1], rh + 2);
            }
        }
    }

    // ---- epilogue ----
    const int gid = lane >> 2, tig = lane & 3;
    const float* be = bias + (size_t)e * NTOT + nb;
#pragma unroll
    for (int mt = 0; mt < 2; mt++) {
        const int rA = wm * 32 + mt * 16 + gid;
        const int rB = rA + 8;
        const int aidA = s_aid[rA], aidB = s_aid[rB];
#pragma unroll
        for (int nt = 0; nt < 8; nt++) {
            const int cl = wn * 64 + nt * 8 + 2 * tig;
            const float b0 = be[cl], b1 = be[cl + 1];
            if constexpr (MODE == 1) {
                if (aidA >= 0) {
                    float g0 = gelu_exact(acc[mt][nt][0] + b0);
                    float g1 = gelu_exact(acc[mt][nt][1] + b1);
                    size_t o = (size_t)(hbase + mb + rA) * HID + nb + cl;
                    *reinterpret_cast<uint32_t*>(g_h16 + o) =
                        pack_h16(__float2half_rn(g0), __float2half_rn(g1));
                }
                if (aidB >= 0) {
                    float g0 = gelu_exact(acc[mt][nt][2] + b0);
                    float g1 = gelu_exact(acc[mt][nt][3] + b1);
                    size_t o = (size_t)(hbase + mb + rB) * HID + nb + cl;
                    *reinterpret_cast<uint32_t*>(g_h16 + o) =
                        pack_h16(__float2half_rn(g0), __float2half_rn(g1));
                }
            } else {
                if (aidA >= 0) {
                    float gate = g_gate[aidA];
                    float* op = out + (size_t)(aidA >> 1) * DIM + nb + cl;
                    red_add_f32x2(op, gate * (acc[mt][nt][0] + b0),
                                      gate * (acc[mt][nt][1] + b1));
                }
                if (aidB >= 0) {
                    float gate = g_gate[aidB];
                    float* op = out + (size_t)(aidB >> 1) * DIM + nb + cl;
                    red_add_f32x2(op, gate * (acc[mt][nt][2] + b0),
                                      gate * (acc[mt][nt][3] + b1));
                }
            }
        }
    }
}

// ---------------- launch ----------------
extern "C" void kernel_launch(void* const* d_in, const int* in_sizes, int n_in,
                              void* d_out, int out_size) {
    const float* x  = (const float*)d_in[0];
    const float* Wg = (const float*)d_in[1];
    const float* bg = (const float*)d_in[2];
    const float* W1 = (const float*)d_in[3];
    const float* b1 = (const float*)d_in[4];
    const float* W2 = (const float*)d_in[5];
    const float* b2 = (const float*)d_in[6];
    float* out = (float*)d_out;

    cudaFuncSetAttribute(k_gemm<DIM, HID, 1>, cudaFuncAttributeMaxDynamicSharedMemorySize, SMEM_DYN);
    cudaFuncSetAttribute(k_gemm<HID, DIM, 2>, cudaFuncAttributeMaxDynamicSharedMemorySize, SMEM_DYN);

    const int MBLK = (T_TOK + BM - 1) / BM;   // 86

    k_prep<<<PREP_TOTAL, 256>>>(x, Wg, bg, W1, W2, out);
    k_gemm<DIM, HID, 1><<<dim3(MBLK, HID / BN, NE), NTHR, SMEM_DYN>>>(b1, out);
    k_gemm<HID, DIM, 2><<<dim3(MBLK, DIM / BN, NE), NTHR, SMEM_DYN>>>(b2, out);
}